// round 5
// baseline (speedup 1.0000x reference)
#include <cuda_runtime.h>
#include <cuda_bf16.h>
#include <cstdint>

#define BB 8
#define NN 256
#define MM 16
#define DD 256

// bf16 centroids scratch: [B][N][D]
__device__ __nv_bfloat16 g_C[BB * NN * DD];

// ============================ helpers ============================
__device__ __forceinline__ uint32_t smem_u32(const void* p) {
    uint32_t a;
    asm("{ .reg .u64 t; cvta.to.shared.u64 t, %1; cvt.u32.u64 %0, t; }"
        : "=r"(a) : "l"(p));
    return a;
}
__device__ __forceinline__ float ex2f(float x) {
    float y; asm("ex2.approx.ftz.f32 %0, %1;" : "=f"(y) : "f"(x)); return y;
}
__device__ __forceinline__ float lg2f(float x) {
    float y; asm("lg2.approx.ftz.f32 %0, %1;" : "=f"(y) : "f"(x)); return y;
}
__device__ __forceinline__ void ldm_x4(uint32_t* r, uint32_t addr) {
    asm volatile("ldmatrix.sync.aligned.m8n8.x4.shared.b16 {%0,%1,%2,%3}, [%4];"
                 : "=r"(r[0]), "=r"(r[1]), "=r"(r[2]), "=r"(r[3])
                 : "r"(addr));
}
__device__ __forceinline__ void mma16816(float* d, const uint32_t* a,
                                         uint32_t b0, uint32_t b1) {
    asm volatile(
        "mma.sync.aligned.m16n8k16.row.col.f32.bf16.bf16.f32 "
        "{%0,%1,%2,%3}, {%4,%5,%6,%7}, {%8,%9}, {%0,%1,%2,%3};"
        : "+f"(d[0]), "+f"(d[1]), "+f"(d[2]), "+f"(d[3])
        : "r"(a[0]), "r"(a[1]), "r"(a[2]), "r"(a[3]), "r"(b0), "r"(b1));
}
__device__ __forceinline__ void cp_async16(uint32_t dst, const void* src) {
    asm volatile("cp.async.cg.shared.global [%0], [%1], 16;"
                 :: "r"(dst), "l"(src) : "memory");
}

// ============================ Kernel 1: centroids + zero out ============================
__global__ void centroid_kernel(const float* __restrict__ E, float* __restrict__ out) {
    int idx = blockIdx.x * blockDim.x + threadIdx.x;  // over B*N*D/4 = 131072
    if (idx == 0) out[0] = 0.0f;
    int d4 = idx & 63;
    int bn = idx >> 6;
    const float4* p = (const float4*)E + (size_t)bn * MM * 64 + d4;
    float4 s = make_float4(0.f, 0.f, 0.f, 0.f);
#pragma unroll
    for (int i = 0; i < MM; i++) {
        float4 v = p[(size_t)i * 64];
        s.x += v.x; s.y += v.y; s.z += v.z; s.w += v.w;
    }
    const float inv = 1.0f / MM;
    __nv_bfloat162 lo = __floats2bfloat162_rn(s.x * inv, s.y * inv);
    __nv_bfloat162 hi = __floats2bfloat162_rn(s.z * inv, s.w * inv);
    uint2 pk; pk.x = *(uint32_t*)&lo; pk.y = *(uint32_t*)&hi;
    *(uint2*)(g_C + (size_t)bn * DD + d4 * 4) = pk;
}

// spacer so ncu's capture slot (4th launch) lands on loss_kernel
__global__ void noop_kernel() {}

// ============================ Kernel 2: pipelined GEMM + full fused LSE ============================
// CTA tile: 64 rows x 256 cols, K pipelined in 4 chunks of 64.
// smem: sqn 256B | SELF 256B | msb 2KB | red 32B | A 2x8KB | B 2x32KB
static constexpr int SQN_OFF  = 0;
static constexpr int SELF_OFF = 256;
static constexpr int MSB_OFF  = 512;     // float2[64][4]
static constexpr int RED_OFF  = 2560;
static constexpr int A_OFF    = 4096;    // 2 bufs x 8192
static constexpr int B_OFF    = 20480;   // 2 bufs x 32768
static constexpr int SMEM_TOTAL = 86016;

__global__ void __launch_bounds__(256, 2) loss_kernel(
    const float* __restrict__ E,
    const float* __restrict__ wp,
    const float* __restrict__ bp,
    float* __restrict__ out)
{
    extern __shared__ char smem[];
    uint32_t sb = smem_u32(smem);
    int tid = threadIdx.x, wid = tid >> 5, L = tid & 31;
    int warpM = wid & 1, warpN = wid >> 1;   // 2x4 warp grid: warp tile 32 rows x 64 cols

    int bx    = blockIdx.x;        // 512 = 8 batches * 64 rowtiles
    int batch = bx >> 6;
    int rt    = bx & 63;

    float w_s = *wp;
    float b_s = *bp;
    float*  sqn  = (float*)(smem + SQN_OFF);
    float*  SELF = (float*)(smem + SELF_OFF);
    float2* msb  = (float2*)(smem + MSB_OFF);
    float*  red  = (float*)(smem + RED_OFF);

    // ---- per-thread load mappings ----
    // A: thread covers row = tid>>2, quarter q = tid&3 (64 fp32 elems per chunk-row / 4)
    int arow = tid >> 2, q = tid & 3;
    const float4* Eg = (const float4*)E +
        ((size_t)(batch * 4096 + rt * 64 + arow)) * 64 + q * 4;
    uint32_t r7 = (uint32_t)(arow & 7);
    uint32_t a_d0 = sb + A_OFF + (uint32_t)arow * 128 + ((((uint32_t)(q * 2))     ^ r7) << 4);
    uint32_t a_d1 = sb + A_OFF + (uint32_t)arow * 128 + ((((uint32_t)(q * 2 + 1)) ^ r7) << 4);
    // B: thread covers centroid n = tid (128B slice per chunk)
    const char* Cg = (const char*)(g_C + (size_t)batch * 65536) + (size_t)tid * 512;
    uint32_t b_d  = sb + B_OFF + (uint32_t)tid * 128;
    uint32_t n7   = (uint32_t)(tid & 7);

    // ---- ldmatrix lane bases ----
    uint32_t aB[2], am[2];
#pragma unroll
    for (int f = 0; f < 2; f++) {
        int r = warpM * 32 + f * 16 + (L & 15);
        aB[f] = sb + A_OFF + (uint32_t)r * 128;
        am[f] = (uint32_t)((L >> 4) ^ (r & 7));
    }
    uint32_t bB[4], bm[4];
#pragma unroll
    for (int nb = 0; nb < 4; nb++) {
        int n = warpN * 64 + nb * 16 + ((L >> 4) << 3) + (L & 7);
        bB[nb] = sb + B_OFF + (uint32_t)n * 128;
        bm[nb] = (uint32_t)(((L >> 3) & 1) ^ (n & 7));
    }

    float acc[2][8][4];
#pragma unroll
    for (int f = 0; f < 2; f++)
#pragma unroll
        for (int j = 0; j < 8; j++)
#pragma unroll
            for (int u = 0; u < 4; u++) acc[f][j][u] = 0.f;

    float sqn_p = 0.f;
    float4 st[4];

    // ---- prologue: chunk 0 ----
    {
#pragma unroll
        for (int un = 0; un < 8; un++)
            cp_async16(b_d + (((uint32_t)un ^ n7) << 4), Cg + un * 16);
        asm volatile("cp.async.commit_group;" ::: "memory");
#pragma unroll
        for (int i = 0; i < 4; i++) st[i] = Eg[i];
#pragma unroll
        for (int i = 0; i < 4; i++)
            sqn_p += st[i].x*st[i].x + st[i].y*st[i].y + st[i].z*st[i].z + st[i].w*st[i].w;
        __nv_bfloat162 c0 = __floats2bfloat162_rn(st[0].x, st[0].y);
        __nv_bfloat162 c1 = __floats2bfloat162_rn(st[0].z, st[0].w);
        __nv_bfloat162 c2 = __floats2bfloat162_rn(st[1].x, st[1].y);
        __nv_bfloat162 c3 = __floats2bfloat162_rn(st[1].z, st[1].w);
        __nv_bfloat162 c4 = __floats2bfloat162_rn(st[2].x, st[2].y);
        __nv_bfloat162 c5 = __floats2bfloat162_rn(st[2].z, st[2].w);
        __nv_bfloat162 c6 = __floats2bfloat162_rn(st[3].x, st[3].y);
        __nv_bfloat162 c7 = __floats2bfloat162_rn(st[3].z, st[3].w);
        uint4 pk0, pk1;
        pk0.x = *(uint32_t*)&c0; pk0.y = *(uint32_t*)&c1;
        pk0.z = *(uint32_t*)&c2; pk0.w = *(uint32_t*)&c3;
        pk1.x = *(uint32_t*)&c4; pk1.y = *(uint32_t*)&c5;
        pk1.z = *(uint32_t*)&c6; pk1.w = *(uint32_t*)&c7;
        *(uint4*)(smem + (a_d0 - sb)) = pk0;
        *(uint4*)(smem + (a_d1 - sb)) = pk1;
        asm volatile("cp.async.wait_group 0;" ::: "memory");
        __syncthreads();
    }

    // ---- pipelined mainloop over 4 K-chunks ----
#pragma unroll
    for (int ck = 0; ck < 4; ck++) {
        uint32_t ap = (uint32_t)(ck & 1) * 8192u;
        uint32_t bpar = (uint32_t)(ck & 1) * 32768u;

        if (ck < 3) {
            uint32_t bd = b_d + (uint32_t)((ck + 1) & 1) * 32768u;
            const char* src = Cg + (ck + 1) * 128;
#pragma unroll
            for (int un = 0; un < 8; un++)
                cp_async16(bd + (((uint32_t)un ^ n7) << 4), src + un * 16);
            asm volatile("cp.async.commit_group;" ::: "memory");
#pragma unroll
            for (int i = 0; i < 4; i++) st[i] = Eg[(ck + 1) * 16 + i];
        }

        // MMA over this chunk: 4 ksteps of k16
#pragma unroll
        for (int ks = 0; ks < 4; ks++) {
            uint32_t o = (uint32_t)(ks * 2);
            uint32_t a0[4], a1[4];
            ldm_x4(a0, aB[0] + ap + (((o) ^ am[0]) << 4));
            ldm_x4(a1, aB[1] + ap + (((o) ^ am[1]) << 4));
#pragma unroll
            for (int nb = 0; nb < 4; nb++) {
                uint32_t bf[4];
                ldm_x4(bf, bB[nb] + bpar + (((o) ^ bm[nb]) << 4));
                mma16816(acc[0][2 * nb],     a0, bf[0], bf[1]);
                mma16816(acc[0][2 * nb + 1], a0, bf[2], bf[3]);
                mma16816(acc[1][2 * nb],     a1, bf[0], bf[1]);
                mma16816(acc[1][2 * nb + 1], a1, bf[2], bf[3]);
            }
        }

        if (ck < 3) {
#pragma unroll
            for (int i = 0; i < 4; i++)
                sqn_p += st[i].x*st[i].x + st[i].y*st[i].y + st[i].z*st[i].z + st[i].w*st[i].w;
            __nv_bfloat162 c0 = __floats2bfloat162_rn(st[0].x, st[0].y);
            __nv_bfloat162 c1 = __floats2bfloat162_rn(st[0].z, st[0].w);
            __nv_bfloat162 c2 = __floats2bfloat162_rn(st[1].x, st[1].y);
            __nv_bfloat162 c3 = __floats2bfloat162_rn(st[1].z, st[1].w);
            __nv_bfloat162 c4 = __floats2bfloat162_rn(st[2].x, st[2].y);
            __nv_bfloat162 c5 = __floats2bfloat162_rn(st[2].z, st[2].w);
            __nv_bfloat162 c6 = __floats2bfloat162_rn(st[3].x, st[3].y);
            __nv_bfloat162 c7 = __floats2bfloat162_rn(st[3].z, st[3].w);
            uint4 pk0, pk1;
            pk0.x = *(uint32_t*)&c0; pk0.y = *(uint32_t*)&c1;
            pk0.z = *(uint32_t*)&c2; pk0.w = *(uint32_t*)&c3;
            pk1.x = *(uint32_t*)&c4; pk1.y = *(uint32_t*)&c5;
            pk1.z = *(uint32_t*)&c6; pk1.w = *(uint32_t*)&c7;
            uint32_t po = (uint32_t)((ck + 1) & 1) * 8192u;
            *(uint4*)(smem + (a_d0 + po - sb)) = pk0;
            *(uint4*)(smem + (a_d1 + po - sb)) = pk1;
            asm volatile("cp.async.wait_group 0;" ::: "memory");
            __syncthreads();
        }
    }

    // ---- finalize sq_norm ----
    sqn_p += __shfl_xor_sync(0xFFFFFFFFu, sqn_p, 1);
    sqn_p += __shfl_xor_sync(0xFFFFFFFFu, sqn_p, 2);
    if ((tid & 3) == 0) sqn[arow] = sqn_p;
    __syncthreads();

    // ---- epilogue: per-warp partial LSE over 64 cols ----
    const float L2E = 1.44269504f, LN2 = 0.69314718f;
    float wdiv = w_s * (1.0f / 15.0f);
#pragma unroll
    for (int f = 0; f < 2; f++) {
        int dk = rt * 4 + warpM * 2 + f;       // global diag col for this frag's 16 rows
        bool own = ((dk >> 6) == warpN);
#pragma unroll
        for (int rh = 0; rh < 2; rh++) {
            int row = warpM * 32 + f * 16 + rh * 8 + (L >> 2);
            float sq = sqn[row];
            float m = -1e30f, sself = 0.f;
#pragma unroll
            for (int j = 0; j < 8; j++) {
#pragma unroll
                for (int cq = 0; cq < 2; cq++) {
                    float v = acc[f][j][rh * 2 + cq];
                    int col = warpN * 64 + (j >> 1) * 16 + (j & 1) * 8 + (L & 3) * 2 + cq;
                    bool dg = (col == dk);
                    float xv = dg ? fmaf(wdiv, fmaf(16.f, v, -sq), b_s)
                                  : fmaf(w_s, v, b_s);
                    if (dg) sself = xv;
                    m = fmaxf(m, xv);
                }
            }
            m = fmaxf(m, __shfl_xor_sync(0xFFFFFFFFu, m, 1));
            m = fmaxf(m, __shfl_xor_sync(0xFFFFFFFFu, m, 2));
            float s = 0.f;
#pragma unroll
            for (int j = 0; j < 8; j++) {
#pragma unroll
                for (int cq = 0; cq < 2; cq++) {
                    float v = acc[f][j][rh * 2 + cq];
                    int col = warpN * 64 + (j >> 1) * 16 + (j & 1) * 8 + (L & 3) * 2 + cq;
                    float xv = (col == dk) ? fmaf(wdiv, fmaf(16.f, v, -sq), b_s)
                                           : fmaf(w_s, v, b_s);
                    s += ex2f((xv - m) * L2E);
                }
            }
            s += __shfl_xor_sync(0xFFFFFFFFu, s, 1);
            s += __shfl_xor_sync(0xFFFFFFFFu, s, 2);
            sself += __shfl_xor_sync(0xFFFFFFFFu, sself, 1);
            sself += __shfl_xor_sync(0xFFFFFFFFu, sself, 2);
            if ((L & 3) == 0) {
                msb[row * 4 + warpN] = make_float2(m, s);
                if (own) SELF[row] = sself;
            }
        }
    }
    __syncthreads();

    // ---- merge 4 warp partials per row, block-reduce, one atomicAdd ----
    float contrib = 0.f;
    if (tid < 64) {
        float2 p0 = msb[tid * 4 + 0], p1 = msb[tid * 4 + 1];
        float2 p2 = msb[tid * 4 + 2], p3 = msb[tid * 4 + 3];
        float m = fmaxf(fmaxf(p0.x, p1.x), fmaxf(p2.x, p3.x));
        float s = p0.y * ex2f((p0.x - m) * L2E) + p1.y * ex2f((p1.x - m) * L2E)
                + p2.y * ex2f((p2.x - m) * L2E) + p3.y * ex2f((p3.x - m) * L2E);
        contrib = m + lg2f(s) * LN2 - SELF[tid];
    }
    contrib += __shfl_xor_sync(0xFFFFFFFFu, contrib, 16);
    contrib += __shfl_xor_sync(0xFFFFFFFFu, contrib, 8);
    contrib += __shfl_xor_sync(0xFFFFFFFFu, contrib, 4);
    contrib += __shfl_xor_sync(0xFFFFFFFFu, contrib, 2);
    contrib += __shfl_xor_sync(0xFFFFFFFFu, contrib, 1);
    if (tid < 64 && L == 0) red[wid] = contrib;
    __syncthreads();
    if (tid == 0) atomicAdd(out, red[0] + red[1]);
}

// ============================ launch ============================
extern "C" void kernel_launch(void* const* d_in, const int* in_sizes, int n_in,
                              void* d_out, int out_size) {
    const float* E  = (const float*)d_in[0];
    const float* wp = (const float*)d_in[1];
    const float* bp = (const float*)d_in[2];
    float* out = (float*)d_out;

    centroid_kernel<<<(BB * NN * DD / 4) / 256, 256>>>(E, out);
    noop_kernel<<<1, 1>>>();
    noop_kernel<<<1, 1>>>();

    cudaFuncSetAttribute(loss_kernel, cudaFuncAttributeMaxDynamicSharedMemorySize, SMEM_TOTAL);
    loss_kernel<<<BB * 64, 256, SMEM_TOTAL>>>(E, wp, bp, out);
}

// round 6
// speedup vs baseline: 1.4517x; 1.4517x over previous
#include <cuda_runtime.h>
#include <cuda_bf16.h>
#include <cstdint>

#define BB 8
#define NN 256
#define MM 16
#define DD 256

// bf16 centroids scratch: [B][N][D]
__device__ __nv_bfloat16 g_C[BB * NN * DD];

// ============================ helpers ============================
__device__ __forceinline__ uint32_t smem_u32(const void* p) {
    uint32_t a;
    asm("{ .reg .u64 t; cvta.to.shared.u64 t, %1; cvt.u32.u64 %0, t; }"
        : "=r"(a) : "l"(p));
    return a;
}
__device__ __forceinline__ float ex2f(float x) {
    float y; asm("ex2.approx.ftz.f32 %0, %1;" : "=f"(y) : "f"(x)); return y;
}
__device__ __forceinline__ float lg2f(float x) {
    float y; asm("lg2.approx.ftz.f32 %0, %1;" : "=f"(y) : "f"(x)); return y;
}
__device__ __forceinline__ void ldm_x4(uint32_t* r, uint32_t addr) {
    asm volatile("ldmatrix.sync.aligned.m8n8.x4.shared.b16 {%0,%1,%2,%3}, [%4];"
                 : "=r"(r[0]), "=r"(r[1]), "=r"(r[2]), "=r"(r[3])
                 : "r"(addr));
}
__device__ __forceinline__ void mma16816(float* d, const uint32_t* a,
                                         uint32_t b0, uint32_t b1) {
    asm volatile(
        "mma.sync.aligned.m16n8k16.row.col.f32.bf16.bf16.f32 "
        "{%0,%1,%2,%3}, {%4,%5,%6,%7}, {%8,%9}, {%0,%1,%2,%3};"
        : "+f"(d[0]), "+f"(d[1]), "+f"(d[2]), "+f"(d[3])
        : "r"(a[0]), "r"(a[1]), "r"(a[2]), "r"(a[3]), "r"(b0), "r"(b1));
}
__device__ __forceinline__ void cp_async16(uint32_t dst, const void* src) {
    asm volatile("cp.async.cg.shared.global [%0], [%1], 16;"
                 :: "r"(dst), "l"(src) : "memory");
}

// ============================ Kernel 1: centroids + zero out ============================
__global__ void centroid_kernel(const float* __restrict__ E, float* __restrict__ out) {
    int idx = blockIdx.x * blockDim.x + threadIdx.x;  // over B*N*D/4 = 131072
    if (idx == 0) out[0] = 0.0f;
    int d4 = idx & 63;
    int bn = idx >> 6;
    const float4* p = (const float4*)E + (size_t)bn * MM * 64 + d4;
    float4 s = make_float4(0.f, 0.f, 0.f, 0.f);
#pragma unroll
    for (int i = 0; i < MM; i++) {
        float4 v = p[(size_t)i * 64];
        s.x += v.x; s.y += v.y; s.z += v.z; s.w += v.w;
    }
    const float inv = 1.0f / MM;
    __nv_bfloat162 lo = __floats2bfloat162_rn(s.x * inv, s.y * inv);
    __nv_bfloat162 hi = __floats2bfloat162_rn(s.z * inv, s.w * inv);
    uint2 pk; pk.x = *(uint32_t*)&lo; pk.y = *(uint32_t*)&hi;
    *(uint2*)(g_C + (size_t)bn * DD + d4 * 4) = pk;
}

// ============================ Kernel 2: GEMM + fused LSE (128x256 tile, 512 thr) ============
static constexpr int SQN_OFF  = 0;        // 128 floats
static constexpr int SELF_OFF = 512;      // 128 floats
static constexpr int MSB_OFF  = 1024;     // float2[128][4] = 4096 B
static constexpr int RED_OFF  = 5120;     // 4 floats
static constexpr int A_OFF    = 8192;     // 128 rows x 512 B = 65536
static constexpr int B_OFF    = 73728;    // 256 rows x 512 B = 131072
static constexpr int SMEM_TOTAL = 204800;

#define SWZ(row, un) ((uint32_t)(row) * 512u + ((((uint32_t)(un)) ^ ((uint32_t)(row) & 7u)) << 4))

__global__ void __launch_bounds__(512, 1) loss_kernel(
    const float* __restrict__ E,
    const float* __restrict__ wp,
    const float* __restrict__ bp,
    float* __restrict__ out)
{
    extern __shared__ char smem[];
    uint32_t sb = smem_u32(smem);
    int tid = threadIdx.x, wid = tid >> 5, L = tid & 31;
    int warpM = wid & 3, warpN = wid >> 2;   // 4x4 warp grid: warp tile 32 rows x 64 cols

    int bx    = blockIdx.x;        // 256 = 8 batches * 32 rowtiles
    int batch = bx >> 5;
    int rt    = bx & 31;           // 128-row tile

    float w_s = *wp;
    float b_s = *bp;
    float*  sqn  = (float*)(smem + SQN_OFF);
    float*  SELF = (float*)(smem + SELF_OFF);
    float2* msb  = (float2*)(smem + MSB_OFF);
    float*  red  = (float*)(smem + RED_OFF);

    // ---- B tile via cp.async: C[batch] [256 x 256] bf16, swizzled (128 KB) ----
    {
        const char* Cg = (const char*)(g_C + (size_t)batch * NN * DD);
#pragma unroll
        for (int it = 0; it < 16; it++) {
            int u = it * 512 + tid;          // 8192 16B units: row*32 + un
            int row = u >> 5, un = u & 31;
            cp_async16(sb + B_OFF + SWZ(row, un), Cg + (size_t)u * 16);
        }
        asm volatile("cp.async.commit_group;" ::: "memory");
    }

    // ---- A tile: 128 rows fp32 -> bf16, fp32 sq_norm (each warp: 1 row per it) ----
    {
        const float4* Eg = (const float4*)E + ((size_t)(batch * 4096 + rt * 128)) * 64;
#pragma unroll
        for (int it = 0; it < 8; it++) {
            int u = it * 512 + tid;          // row = it*16 + wid, un = L
            int row = it * 16 + wid;
            float4 v0 = Eg[u * 2];
            float4 v1 = Eg[u * 2 + 1];
            float ps = v0.x*v0.x + v0.y*v0.y + v0.z*v0.z + v0.w*v0.w
                     + v1.x*v1.x + v1.y*v1.y + v1.z*v1.z + v1.w*v1.w;
            ps += __shfl_xor_sync(0xFFFFFFFFu, ps, 16);
            ps += __shfl_xor_sync(0xFFFFFFFFu, ps, 8);
            ps += __shfl_xor_sync(0xFFFFFFFFu, ps, 4);
            ps += __shfl_xor_sync(0xFFFFFFFFu, ps, 2);
            ps += __shfl_xor_sync(0xFFFFFFFFu, ps, 1);
            if (L == 0) sqn[row] = ps;

            __nv_bfloat162 p0 = __floats2bfloat162_rn(v0.x, v0.y);
            __nv_bfloat162 p1 = __floats2bfloat162_rn(v0.z, v0.w);
            __nv_bfloat162 p2 = __floats2bfloat162_rn(v1.x, v1.y);
            __nv_bfloat162 p3 = __floats2bfloat162_rn(v1.z, v1.w);
            uint4 pk;
            pk.x = *(uint32_t*)&p0; pk.y = *(uint32_t*)&p1;
            pk.z = *(uint32_t*)&p2; pk.w = *(uint32_t*)&p3;
            *(uint4*)(smem + A_OFF + SWZ(row, L)) = pk;
        }
    }
    asm volatile("cp.async.wait_group 0;" ::: "memory");
    __syncthreads();

    // ---- per-lane ldmatrix addressing (verified formulas) ----
    uint32_t arsk = (uint32_t)((L >> 4) ^ (L & 7));
    uint32_t aB0  = sb + A_OFF + (uint32_t)(warpM * 32 + (L & 15)) * 512u;
    uint32_t aB1  = aB0 + 16 * 512;
    uint32_t brsk = (uint32_t)(((L >> 3) & 1) ^ (L & 7));
    uint32_t bB[4];
#pragma unroll
    for (int nb = 0; nb < 4; nb++)
        bB[nb] = sb + B_OFF +
                 (uint32_t)(warpN * 64 + nb * 16 + ((L >> 4) << 3) + (L & 7)) * 512u;

    float acc[2][8][4];
#pragma unroll
    for (int f = 0; f < 2; f++)
#pragma unroll
        for (int j = 0; j < 8; j++)
#pragma unroll
            for (int u = 0; u < 4; u++) acc[f][j][u] = 0.f;

    // ---- mainloop: K=256 in 16 ksteps of k16 ----
#pragma unroll 4
    for (int ks = 0; ks < 16; ks++) {
        uint32_t ku = (uint32_t)(ks * 2);
        uint32_t xa = ((ku ^ arsk) << 4);
        uint32_t xb = ((ku ^ brsk) << 4);
        uint32_t a0[4], a1[4];
        ldm_x4(a0, aB0 + xa);
        ldm_x4(a1, aB1 + xa);
#pragma unroll
        for (int nb = 0; nb < 4; nb++) {
            uint32_t bf[4];
            ldm_x4(bf, bB[nb] + xb);
            mma16816(acc[0][2 * nb],     a0, bf[0], bf[1]);
            mma16816(acc[0][2 * nb + 1], a0, bf[2], bf[3]);
            mma16816(acc[1][2 * nb],     a1, bf[0], bf[1]);
            mma16816(acc[1][2 * nb + 1], a1, bf[2], bf[3]);
        }
    }

    // ---- epilogue: per-warp partial LSE over its 64 cols ----
    const float L2E = 1.44269504f, LN2 = 0.69314718f;
    float wdiv = w_s * (1.0f / 15.0f);
#pragma unroll
    for (int f = 0; f < 2; f++) {
        int dk  = rt * 8 + warpM * 2 + f;       // global diag col for this frag's 16 rows
        bool own = ((dk >> 6) == warpN);
#pragma unroll
        for (int rh = 0; rh < 2; rh++) {
            int row = warpM * 32 + f * 16 + rh * 8 + (L >> 2);   // local row [0,128)
            float sq = sqn[row];
            float m = -1e30f, sself = 0.f;
#pragma unroll
            for (int j = 0; j < 8; j++) {
#pragma unroll
                for (int cq = 0; cq < 2; cq++) {
                    float v = acc[f][j][rh * 2 + cq];
                    int col = warpN * 64 + (j >> 1) * 16 + (j & 1) * 8 + (L & 3) * 2 + cq;
                    bool dg = (col == dk);
                    float xv = dg ? fmaf(wdiv, fmaf(16.f, v, -sq), b_s)
                                  : fmaf(w_s, v, b_s);
                    if (dg) sself = xv;
                    m = fmaxf(m, xv);
                }
            }
            m = fmaxf(m, __shfl_xor_sync(0xFFFFFFFFu, m, 1));
            m = fmaxf(m, __shfl_xor_sync(0xFFFFFFFFu, m, 2));
            float s = 0.f;
#pragma unroll
            for (int j = 0; j < 8; j++) {
#pragma unroll
                for (int cq = 0; cq < 2; cq++) {
                    float v = acc[f][j][rh * 2 + cq];
                    int col = warpN * 64 + (j >> 1) * 16 + (j & 1) * 8 + (L & 3) * 2 + cq;
                    float xv = (col == dk) ? fmaf(wdiv, fmaf(16.f, v, -sq), b_s)
                                           : fmaf(w_s, v, b_s);
                    s += ex2f((xv - m) * L2E);
                }
            }
            s += __shfl_xor_sync(0xFFFFFFFFu, s, 1);
            s += __shfl_xor_sync(0xFFFFFFFFu, s, 2);
            sself += __shfl_xor_sync(0xFFFFFFFFu, sself, 1);
            sself += __shfl_xor_sync(0xFFFFFFFFu, sself, 2);
            if ((L & 3) == 0) {
                msb[row * 4 + warpN] = make_float2(m, s);
                if (own) SELF[row] = sself;
            }
        }
    }
    __syncthreads();

    // ---- merge 4 warpN partials per row, block-reduce, one atomicAdd ----
    float contrib = 0.f;
    if (tid < 128) {
        float2 p0 = msb[tid * 4 + 0], p1 = msb[tid * 4 + 1];
        float2 p2 = msb[tid * 4 + 2], p3 = msb[tid * 4 + 3];
        float m = fmaxf(fmaxf(p0.x, p1.x), fmaxf(p2.x, p3.x));
        float s = p0.y * ex2f((p0.x - m) * L2E) + p1.y * ex2f((p1.x - m) * L2E)
                + p2.y * ex2f((p2.x - m) * L2E) + p3.y * ex2f((p3.x - m) * L2E);
        contrib = m + lg2f(s) * LN2 - SELF[tid];
    }
    if (tid < 128) {
        contrib += __shfl_xor_sync(0xFFFFFFFFu, contrib, 16);
        contrib += __shfl_xor_sync(0xFFFFFFFFu, contrib, 8);
        contrib += __shfl_xor_sync(0xFFFFFFFFu, contrib, 4);
        contrib += __shfl_xor_sync(0xFFFFFFFFu, contrib, 2);
        contrib += __shfl_xor_sync(0xFFFFFFFFu, contrib, 1);
        if (L == 0) red[wid] = contrib;
    }
    __syncthreads();
    if (tid == 0) atomicAdd(out, red[0] + red[1] + red[2] + red[3]);
}

// ============================ launch ============================
extern "C" void kernel_launch(void* const* d_in, const int* in_sizes, int n_in,
                              void* d_out, int out_size) {
    const float* E  = (const float*)d_in[0];
    const float* wp = (const float*)d_in[1];
    const float* bp = (const float*)d_in[2];
    float* out = (float*)d_out;

    centroid_kernel<<<(BB * NN * DD / 4) / 256, 256>>>(E, out);

    cudaFuncSetAttribute(loss_kernel, cudaFuncAttributeMaxDynamicSharedMemorySize, SMEM_TOTAL);
    loss_kernel<<<BB * 32, 512, SMEM_TOTAL>>>(E, wp, bp, out);
}

// round 7
// speedup vs baseline: 1.4672x; 1.0107x over previous
#include <cuda_runtime.h>
#include <cuda_bf16.h>
#include <cstdint>

#define BB 8
#define NN 256
#define MM 16
#define DD 256

// bf16 centroids scratch: [B][N][D]
__device__ __nv_bfloat16 g_C[BB * NN * DD];

// ============================ helpers ============================
__device__ __forceinline__ uint32_t smem_u32(const void* p) {
    uint32_t a;
    asm("{ .reg .u64 t; cvta.to.shared.u64 t, %1; cvt.u32.u64 %0, t; }"
        : "=r"(a) : "l"(p));
    return a;
}
__device__ __forceinline__ float ex2f(float x) {
    float y; asm("ex2.approx.ftz.f32 %0, %1;" : "=f"(y) : "f"(x)); return y;
}
__device__ __forceinline__ float lg2f(float x) {
    float y; asm("lg2.approx.ftz.f32 %0, %1;" : "=f"(y) : "f"(x)); return y;
}
__device__ __forceinline__ void ldm_x4(uint32_t* r, uint32_t addr) {
    asm volatile("ldmatrix.sync.aligned.m8n8.x4.shared.b16 {%0,%1,%2,%3}, [%4];"
                 : "=r"(r[0]), "=r"(r[1]), "=r"(r[2]), "=r"(r[3])
                 : "r"(addr));
}
__device__ __forceinline__ void mma16816(float* d, const uint32_t* a,
                                         uint32_t b0, uint32_t b1) {
    asm volatile(
        "mma.sync.aligned.m16n8k16.row.col.f32.bf16.bf16.f32 "
        "{%0,%1,%2,%3}, {%4,%5,%6,%7}, {%8,%9}, {%0,%1,%2,%3};"
        : "+f"(d[0]), "+f"(d[1]), "+f"(d[2]), "+f"(d[3])
        : "r"(a[0]), "r"(a[1]), "r"(a[2]), "r"(a[3]), "r"(b0), "r"(b1));
}
__device__ __forceinline__ void cp_async16(uint32_t dst, const void* src) {
    asm volatile("cp.async.cg.shared.global [%0], [%1], 16;"
                 :: "r"(dst), "l"(src) : "memory");
}

// ============================ Kernel 1: centroids + zero out ============================
__global__ void centroid_kernel(const float* __restrict__ E, float* __restrict__ out) {
    int idx = blockIdx.x * blockDim.x + threadIdx.x;  // over B*N*D/4 = 131072
    if (idx == 0) out[0] = 0.0f;
    int d4 = idx & 63;
    int bn = idx >> 6;
    const float4* p = (const float4*)E + (size_t)bn * MM * 64 + d4;
    float4 s = make_float4(0.f, 0.f, 0.f, 0.f);
#pragma unroll
    for (int i = 0; i < MM; i++) {
        float4 v = p[(size_t)i * 64];
        s.x += v.x; s.y += v.y; s.z += v.z; s.w += v.w;
    }
    const float inv = 1.0f / MM;
    __nv_bfloat162 lo = __floats2bfloat162_rn(s.x * inv, s.y * inv);
    __nv_bfloat162 hi = __floats2bfloat162_rn(s.z * inv, s.w * inv);
    uint2 pk; pk.x = *(uint32_t*)&lo; pk.y = *(uint32_t*)&hi;
    *(uint2*)(g_C + (size_t)bn * DD + d4 * 4) = pk;
}

// ============================ Kernel 2: persistent GEMM + fused LSE ==================
// Grid 128: each CTA does 2 row-tiles (128x256) of the SAME batch; B loaded once.
static constexpr int SQN_OFF  = 0;        // 128 floats
static constexpr int SELF_OFF = 512;      // 128 floats
static constexpr int MSB_OFF  = 1024;     // float2[128][4] = 4096 B
static constexpr int RED_OFF  = 5120;     // 4 floats
static constexpr int A_OFF    = 8192;     // 128 rows x 512 B = 65536
static constexpr int B_OFF    = 73728;    // 256 rows x 512 B = 131072
static constexpr int SMEM_TOTAL = 204800;

#define SWZ(row, un) ((uint32_t)(row) * 512u + ((((uint32_t)(un)) ^ ((uint32_t)(row) & 7u)) << 4))

__global__ void __launch_bounds__(512, 1) loss_kernel(
    const float* __restrict__ E,
    const float* __restrict__ wp,
    const float* __restrict__ bp,
    float* __restrict__ out)
{
    extern __shared__ char smem[];
    uint32_t sb = smem_u32(smem);
    int tid = threadIdx.x, wid = tid >> 5, L = tid & 31;
    int warpM = wid & 3, warpN = wid >> 2;   // 4x4 warp grid: warp tile 32 rows x 64 cols

    int bx    = blockIdx.x;        // 128 CTAs
    int batch = bx >> 4;
    int rtb   = (bx & 15) * 2;     // first of two 128-row tiles

    float w_s = *wp;
    float b_s = *bp;
    float*  sqn  = (float*)(smem + SQN_OFF);
    float*  SELF = (float*)(smem + SELF_OFF);
    float2* msb  = (float2*)(smem + MSB_OFF);
    float*  red  = (float*)(smem + RED_OFF);

    // ---- B tile via cp.async: C[batch] [256 x 256] bf16, swizzled (128 KB), ONCE ----
    {
        const char* Cg = (const char*)(g_C + (size_t)batch * NN * DD);
#pragma unroll
        for (int it = 0; it < 16; it++) {
            int u = it * 512 + tid;          // 8192 16B units: row*32 + un
            int row = u >> 5, un = u & 31;
            cp_async16(sb + B_OFF + SWZ(row, un), Cg + (size_t)u * 16);
        }
        asm volatile("cp.async.commit_group;" ::: "memory");
    }

    // ---- invariant per-lane addressing ----
    int arow = tid >> 2, q = tid & 3;        // A-load: 4 threads per row
    uint32_t arsk = (uint32_t)((L >> 4) ^ (L & 7));
    uint32_t aB0  = sb + A_OFF + (uint32_t)(warpM * 32 + (L & 15)) * 512u;
    uint32_t aB1  = aB0 + 16 * 512;
    uint32_t brsk = (uint32_t)(((L >> 3) & 1) ^ (L & 7));
    uint32_t bB[4];
#pragma unroll
    for (int nb = 0; nb < 4; nb++)
        bB[nb] = sb + B_OFF +
                 (uint32_t)(warpN * 64 + nb * 16 + ((L >> 4) << 3) + (L & 7)) * 512u;

    const float L2E = 1.44269504f, LN2 = 0.69314718f;
    float wdiv = w_s * (1.0f / 15.0f);
    float total = 0.f;

    for (int t2 = 0; t2 < 2; t2++) {
        int rt = rtb + t2;

        // ---- A tile: each thread = 1/4 row, 16 float4, reg-chain sq_norm ----
        {
            const float4* Eg = (const float4*)E +
                ((size_t)(batch * 4096 + rt * 128 + arow)) * 64;
            float sqp = 0.f;
#pragma unroll
            for (int i = 0; i < 8; i++) {
                int u = i * 4 + q;                   // dest 16B unit
                float4 v0 = Eg[u * 2];
                float4 v1 = Eg[u * 2 + 1];
                sqp += v0.x*v0.x + v0.y*v0.y + v0.z*v0.z + v0.w*v0.w
                     + v1.x*v1.x + v1.y*v1.y + v1.z*v1.z + v1.w*v1.w;
                __nv_bfloat162 p0 = __floats2bfloat162_rn(v0.x, v0.y);
                __nv_bfloat162 p1 = __floats2bfloat162_rn(v0.z, v0.w);
                __nv_bfloat162 p2 = __floats2bfloat162_rn(v1.x, v1.y);
                __nv_bfloat162 p3 = __floats2bfloat162_rn(v1.z, v1.w);
                uint4 pk;
                pk.x = *(uint32_t*)&p0; pk.y = *(uint32_t*)&p1;
                pk.z = *(uint32_t*)&p2; pk.w = *(uint32_t*)&p3;
                *(uint4*)(smem + A_OFF + SWZ(arow, u)) = pk;
            }
            sqp += __shfl_xor_sync(0xFFFFFFFFu, sqp, 1);
            sqp += __shfl_xor_sync(0xFFFFFFFFu, sqp, 2);
            if (q == 0) sqn[arow] = sqp;
        }
        if (t2 == 0) { asm volatile("cp.async.wait_group 0;" ::: "memory"); }
        __syncthreads();

        // ---- mainloop: K=256 in 16 ksteps of k16 ----
        float acc[2][8][4];
#pragma unroll
        for (int f = 0; f < 2; f++)
#pragma unroll
            for (int j = 0; j < 8; j++)
#pragma unroll
                for (int u = 0; u < 4; u++) acc[f][j][u] = 0.f;

#pragma unroll 4
        for (int ks = 0; ks < 16; ks++) {
            uint32_t ku = (uint32_t)(ks * 2);
            uint32_t xa = ((ku ^ arsk) << 4);
            uint32_t xb = ((ku ^ brsk) << 4);
            uint32_t a0[4], a1[4];
            ldm_x4(a0, aB0 + xa);
            ldm_x4(a1, aB1 + xa);
#pragma unroll
            for (int nb = 0; nb < 4; nb++) {
                uint32_t bf[4];
                ldm_x4(bf, bB[nb] + xb);
                mma16816(acc[0][2 * nb],     a0, bf[0], bf[1]);
                mma16816(acc[0][2 * nb + 1], a0, bf[2], bf[3]);
                mma16816(acc[1][2 * nb],     a1, bf[0], bf[1]);
                mma16816(acc[1][2 * nb + 1], a1, bf[2], bf[3]);
            }
        }

        // ---- epilogue: per-warp partial LSE over its 64 cols ----
#pragma unroll
        for (int f = 0; f < 2; f++) {
            int dk  = rt * 8 + warpM * 2 + f;
            bool own = ((dk >> 6) == warpN);
#pragma unroll
            for (int rh = 0; rh < 2; rh++) {
                int row = warpM * 32 + f * 16 + rh * 8 + (L >> 2);
                float sq = sqn[row];
                float m = -1e30f, sself = 0.f;
#pragma unroll
                for (int j = 0; j < 8; j++) {
#pragma unroll
                    for (int cq = 0; cq < 2; cq++) {
                        float v = acc[f][j][rh * 2 + cq];
                        int col = warpN * 64 + (j >> 1) * 16 + (j & 1) * 8 + (L & 3) * 2 + cq;
                        bool dg = (col == dk);
                        float xv = dg ? fmaf(wdiv, fmaf(16.f, v, -sq), b_s)
                                      : fmaf(w_s, v, b_s);
                        if (dg) sself = xv;
                        m = fmaxf(m, xv);
                    }
                }
                m = fmaxf(m, __shfl_xor_sync(0xFFFFFFFFu, m, 1));
                m = fmaxf(m, __shfl_xor_sync(0xFFFFFFFFu, m, 2));
                float s = 0.f;
#pragma unroll
                for (int j = 0; j < 8; j++) {
#pragma unroll
                    for (int cq = 0; cq < 2; cq++) {
                        float v = acc[f][j][rh * 2 + cq];
                        int col = warpN * 64 + (j >> 1) * 16 + (j & 1) * 8 + (L & 3) * 2 + cq;
                        float xv = (col == dk) ? fmaf(wdiv, fmaf(16.f, v, -sq), b_s)
                                               : fmaf(w_s, v, b_s);
                        s += ex2f((xv - m) * L2E);
                    }
                }
                s += __shfl_xor_sync(0xFFFFFFFFu, s, 1);
                s += __shfl_xor_sync(0xFFFFFFFFu, s, 2);
                sself += __shfl_xor_sync(0xFFFFFFFFu, sself, 1);
                sself += __shfl_xor_sync(0xFFFFFFFFu, sself, 2);
                if ((L & 3) == 0) {
                    msb[row * 4 + warpN] = make_float2(m, s);
                    if (own) SELF[row] = sself;
                }
            }
        }
        __syncthreads();

        // ---- merge 4 warpN partials per row, reduce ----
        if (tid < 128) {
            float2 p0 = msb[tid * 4 + 0], p1 = msb[tid * 4 + 1];
            float2 p2 = msb[tid * 4 + 2], p3 = msb[tid * 4 + 3];
            float m = fmaxf(fmaxf(p0.x, p1.x), fmaxf(p2.x, p3.x));
            float s = p0.y * ex2f((p0.x - m) * L2E) + p1.y * ex2f((p1.x - m) * L2E)
                    + p2.y * ex2f((p2.x - m) * L2E) + p3.y * ex2f((p3.x - m) * L2E);
            float contrib = m + lg2f(s) * LN2 - SELF[tid];
            contrib += __shfl_xor_sync(0xFFFFFFFFu, contrib, 16);
            contrib += __shfl_xor_sync(0xFFFFFFFFu, contrib, 8);
            contrib += __shfl_xor_sync(0xFFFFFFFFu, contrib, 4);
            contrib += __shfl_xor_sync(0xFFFFFFFFu, contrib, 2);
            contrib += __shfl_xor_sync(0xFFFFFFFFu, contrib, 1);
            if (L == 0) red[wid] = contrib;
        }
        __syncthreads();
        if (tid == 0) total += red[0] + red[1] + red[2] + red[3];
        __syncthreads();   // protect smem reuse (sqn/msb/SELF/A) for next tile
    }

    if (tid == 0) atomicAdd(out, total);
}

// ============================ launch ============================
extern "C" void kernel_launch(void* const* d_in, const int* in_sizes, int n_in,
                              void* d_out, int out_size) {
    const float* E  = (const float*)d_in[0];
    const float* wp = (const float*)d_in[1];
    const float* bp = (const float*)d_in[2];
    float* out = (float*)d_out;

    centroid_kernel<<<(BB * NN * DD / 4) / 256, 256>>>(E, out);

    cudaFuncSetAttribute(loss_kernel, cudaFuncAttributeMaxDynamicSharedMemorySize, SMEM_TOTAL);
    loss_kernel<<<128, 512, SMEM_TOTAL>>>(E, wp, bp, out);
}

// round 8
// speedup vs baseline: 1.5563x; 1.0607x over previous
#include <cuda_runtime.h>
#include <cuda_bf16.h>
#include <cstdint>

#define BB 8
#define NN 256
#define MM 16
#define DD 256

// scratch: bf16 centroids, bf16 embeddings, fp32 row sq_norms
__device__ __align__(16) __nv_bfloat16 g_C[BB * NN * DD];
__device__ __align__(16) __nv_bfloat16 g_Ebf[BB * NN * MM * DD];
__device__ float g_SQN[BB * NN * MM];

// ============================ helpers ============================
__device__ __forceinline__ uint32_t smem_u32(const void* p) {
    uint32_t a;
    asm("{ .reg .u64 t; cvta.to.shared.u64 t, %1; cvt.u32.u64 %0, t; }"
        : "=r"(a) : "l"(p));
    return a;
}
__device__ __forceinline__ float ex2f(float x) {
    float y; asm("ex2.approx.ftz.f32 %0, %1;" : "=f"(y) : "f"(x)); return y;
}
__device__ __forceinline__ float lg2f(float x) {
    float y; asm("lg2.approx.ftz.f32 %0, %1;" : "=f"(y) : "f"(x)); return y;
}
__device__ __forceinline__ void ldm_x4(uint32_t* r, uint32_t addr) {
    asm volatile("ldmatrix.sync.aligned.m8n8.x4.shared.b16 {%0,%1,%2,%3}, [%4];"
                 : "=r"(r[0]), "=r"(r[1]), "=r"(r[2]), "=r"(r[3])
                 : "r"(addr));
}
__device__ __forceinline__ void mma16816(float* d, const uint32_t* a,
                                         uint32_t b0, uint32_t b1) {
    asm volatile(
        "mma.sync.aligned.m16n8k16.row.col.f32.bf16.bf16.f32 "
        "{%0,%1,%2,%3}, {%4,%5,%6,%7}, {%8,%9}, {%0,%1,%2,%3};"
        : "+f"(d[0]), "+f"(d[1]), "+f"(d[2]), "+f"(d[3])
        : "r"(a[0]), "r"(a[1]), "r"(a[2]), "r"(a[3]), "r"(b0), "r"(b1));
}
__device__ __forceinline__ void cp_async16(uint32_t dst, const void* src) {
    asm volatile("cp.async.cg.shared.global [%0], [%1], 16;"
                 :: "r"(dst), "l"(src) : "memory");
}

// ============================ Kernel 1: centroids + bf16 E + sq_norms ============================
// 256 threads = 4 bn-groups x 64 threads (one float4-column each)
__global__ void centroid_kernel(const float* __restrict__ E, float* __restrict__ out) {
    __shared__ float ssq[4][16][68];   // padded: stride 68 floats avoids bank repeats over m
    int tid = threadIdx.x;
    int idx = blockIdx.x * 256 + tid;
    if (idx == 0) out[0] = 0.f;
    int d4 = idx & 63, bn = idx >> 6;
    int g  = tid >> 6;
    const float4* p = (const float4*)E + (size_t)bn * MM * 64 + d4;
    float4 s = make_float4(0.f, 0.f, 0.f, 0.f);
#pragma unroll
    for (int m = 0; m < MM; m++) {
        float4 v = p[m * 64];
        s.x += v.x; s.y += v.y; s.z += v.z; s.w += v.w;
        ssq[g][m][d4] = v.x*v.x + v.y*v.y + v.z*v.z + v.w*v.w;
        __nv_bfloat162 lo = __floats2bfloat162_rn(v.x, v.y);
        __nv_bfloat162 hi = __floats2bfloat162_rn(v.z, v.w);
        uint2 pk; pk.x = *(uint32_t*)&lo; pk.y = *(uint32_t*)&hi;
        *(uint2*)(g_Ebf + ((size_t)bn * MM + m) * DD + d4 * 4) = pk;
    }
    const float inv = 1.0f / MM;
    __nv_bfloat162 lo = __floats2bfloat162_rn(s.x * inv, s.y * inv);
    __nv_bfloat162 hi = __floats2bfloat162_rn(s.z * inv, s.w * inv);
    uint2 pk; pk.x = *(uint32_t*)&lo; pk.y = *(uint32_t*)&hi;
    *(uint2*)(g_C + (size_t)bn * DD + d4 * 4) = pk;

    __syncthreads();
    // reduce sq_norms: 64 rows per block, 4 threads per row
    int lr = tid >> 2, q = tid & 3;
    float acc = 0.f;
#pragma unroll
    for (int k = 0; k < 16; k++) acc += ssq[lr >> 4][lr & 15][q * 16 + k];
    acc += __shfl_xor_sync(0xFFFFFFFFu, acc, 1);
    acc += __shfl_xor_sync(0xFFFFFFFFu, acc, 2);
    if (q == 0) g_SQN[blockIdx.x * 64 + lr] = acc;
}

// ============================ Kernel 2: persistent GEMM + fused LSE ==================
static constexpr int SQN0_OFF = 0;        // 128 floats
static constexpr int SQN1_OFF = 512;      // 128 floats
static constexpr int MSB_OFF  = 1024;     // float2[128][4] = 4096 B
static constexpr int SELF_OFF = 5120;     // 128 floats
static constexpr int RED_OFF  = 5632;     // 4 floats
static constexpr int A_OFF    = 8192;     // 128 rows x 512 B = 65536
static constexpr int B_OFF    = 73728;    // 256 rows x 512 B = 131072
static constexpr int SMEM_TOTAL = 204800;

#define SWZ(row, un) ((uint32_t)(row) * 512u + ((((uint32_t)(un)) ^ ((uint32_t)(row) & 7u)) << 4))

__global__ void __launch_bounds__(512, 1) loss_kernel(
    const float* __restrict__ wp,
    const float* __restrict__ bp,
    float* __restrict__ out)
{
    extern __shared__ char smem[];
    uint32_t sb = smem_u32(smem);
    int tid = threadIdx.x, wid = tid >> 5, L = tid & 31;
    int warpM = wid & 3, warpN = wid >> 2;   // 4x4 warp grid: warp tile 32 rows x 64 cols

    int bx    = blockIdx.x;        // 128 CTAs
    int batch = bx >> 4;
    int rtb   = (bx & 15) * 2;     // first of two 128-row tiles

    float w_s = *wp;
    float b_s = *bp;
    float*  sqn0 = (float*)(smem + SQN0_OFF);
    float*  sqn1 = (float*)(smem + SQN1_OFF);
    float2* msb  = (float2*)(smem + MSB_OFF);
    float*  SELF = (float*)(smem + SELF_OFF);
    float*  red  = (float*)(smem + RED_OFF);

    // ---- prologue: B tile (128 KB) + A tile 0 (64 KB) via cp.async; both sqn tiles ----
    {
        const char* Cg = (const char*)(g_C + (size_t)batch * NN * DD);
#pragma unroll
        for (int it = 0; it < 16; it++) {
            int u = it * 512 + tid;
            cp_async16(sb + B_OFF + SWZ(u >> 5, u & 31), Cg + (size_t)u * 16);
        }
        const char* Ag = (const char*)(g_Ebf + ((size_t)(batch * 4096 + rtb * 128)) * DD);
#pragma unroll
        for (int it = 0; it < 8; it++) {
            int u = it * 512 + tid;
            cp_async16(sb + A_OFF + SWZ(u >> 5, u & 31), Ag + (size_t)u * 16);
        }
        asm volatile("cp.async.commit_group;" ::: "memory");
        if (tid < 128) {
            int base = batch * 4096 + rtb * 128;
            sqn0[tid] = g_SQN[base + tid];
            sqn1[tid] = g_SQN[base + 128 + tid];
        }
        asm volatile("cp.async.wait_group 0;" ::: "memory");
    }
    __syncthreads();

    // ---- invariant per-lane ldmatrix addressing ----
    uint32_t arsk = (uint32_t)((L >> 4) ^ (L & 7));
    uint32_t aB0  = sb + A_OFF + (uint32_t)(warpM * 32 + (L & 15)) * 512u;
    uint32_t aB1  = aB0 + 16 * 512;
    uint32_t brsk = (uint32_t)(((L >> 3) & 1) ^ (L & 7));
    uint32_t bB[4];
#pragma unroll
    for (int nb = 0; nb < 4; nb++)
        bB[nb] = sb + B_OFF +
                 (uint32_t)(warpN * 64 + nb * 16 + ((L >> 4) << 3) + (L & 7)) * 512u;

    const float L2E = 1.44269504f, LN2 = 0.69314718f;
    float wdiv = w_s * (1.0f / 15.0f);
    float total = 0.f;

    for (int t2 = 0; t2 < 2; t2++) {
        int rt = rtb + t2;
        float* sqn = t2 ? sqn1 : sqn0;

        // ---- mainloop: K=256 in 16 ksteps of k16 ----
        float acc[2][8][4];
#pragma unroll
        for (int f = 0; f < 2; f++)
#pragma unroll
            for (int j = 0; j < 8; j++)
#pragma unroll
                for (int u = 0; u < 4; u++) acc[f][j][u] = 0.f;

#pragma unroll 4
        for (int ks = 0; ks < 16; ks++) {
            uint32_t ku = (uint32_t)(ks * 2);
            uint32_t xa = ((ku ^ arsk) << 4);
            uint32_t xb = ((ku ^ brsk) << 4);
            uint32_t a0[4], a1[4];
            ldm_x4(a0, aB0 + xa);
            ldm_x4(a1, aB1 + xa);
#pragma unroll
            for (int nb = 0; nb < 4; nb++) {
                uint32_t bf[4];
                ldm_x4(bf, bB[nb] + xb);
                mma16816(acc[0][2 * nb],     a0, bf[0], bf[1]);
                mma16816(acc[0][2 * nb + 1], a0, bf[2], bf[3]);
                mma16816(acc[1][2 * nb],     a1, bf[0], bf[1]);
                mma16816(acc[1][2 * nb + 1], a1, bf[2], bf[3]);
            }
        }
        __syncthreads();   // all warps done reading A smem

        // prefetch next tile's A under the epilogue
        if (t2 == 0) {
            const char* Ag = (const char*)(g_Ebf +
                ((size_t)(batch * 4096 + (rtb + 1) * 128)) * DD);
#pragma unroll
            for (int it = 0; it < 8; it++) {
                int u = it * 512 + tid;
                cp_async16(sb + A_OFF + SWZ(u >> 5, u & 31), Ag + (size_t)u * 16);
            }
            asm volatile("cp.async.commit_group;" ::: "memory");
        }

        // ---- epilogue: per-warp partial LSE over its 64 cols ----
#pragma unroll
        for (int f = 0; f < 2; f++) {
            int dk  = rt * 8 + warpM * 2 + f;
            bool own = ((dk >> 6) == warpN);
#pragma unroll
            for (int rh = 0; rh < 2; rh++) {
                int row = warpM * 32 + f * 16 + rh * 8 + (L >> 2);
                float sq = sqn[row];
                float m = -1e30f, sself = 0.f;
#pragma unroll
                for (int j = 0; j < 8; j++) {
#pragma unroll
                    for (int cq = 0; cq < 2; cq++) {
                        float v = acc[f][j][rh * 2 + cq];
                        int col = warpN * 64 + (j >> 1) * 16 + (j & 1) * 8 + (L & 3) * 2 + cq;
                        bool dg = (col == dk);
                        float xv = dg ? fmaf(wdiv, fmaf(16.f, v, -sq), b_s)
                                      : fmaf(w_s, v, b_s);
                        if (dg) sself = xv;
                        m = fmaxf(m, xv);
                    }
                }
                m = fmaxf(m, __shfl_xor_sync(0xFFFFFFFFu, m, 1));
                m = fmaxf(m, __shfl_xor_sync(0xFFFFFFFFu, m, 2));
                float s = 0.f;
#pragma unroll
                for (int j = 0; j < 8; j++) {
#pragma unroll
                    for (int cq = 0; cq < 2; cq++) {
                        float v = acc[f][j][rh * 2 + cq];
                        int col = warpN * 64 + (j >> 1) * 16 + (j & 1) * 8 + (L & 3) * 2 + cq;
                        float xv = (col == dk) ? fmaf(wdiv, fmaf(16.f, v, -sq), b_s)
                                               : fmaf(w_s, v, b_s);
                        s += ex2f((xv - m) * L2E);
                    }
                }
                s += __shfl_xor_sync(0xFFFFFFFFu, s, 1);
                s += __shfl_xor_sync(0xFFFFFFFFu, s, 2);
                sself += __shfl_xor_sync(0xFFFFFFFFu, sself, 1);
                sself += __shfl_xor_sync(0xFFFFFFFFu, sself, 2);
                if ((L & 3) == 0) {
                    msb[row * 4 + warpN] = make_float2(m, s);
                    if (own) SELF[row] = sself;
                }
            }
        }
        __syncthreads();

        // ---- merge 4 warpN partials per row, reduce ----
        if (tid < 128) {
            float2 p0 = msb[tid * 4 + 0], p1 = msb[tid * 4 + 1];
            float2 p2 = msb[tid * 4 + 2], p3 = msb[tid * 4 + 3];
            float m = fmaxf(fmaxf(p0.x, p1.x), fmaxf(p2.x, p3.x));
            float s = p0.y * ex2f((p0.x - m) * L2E) + p1.y * ex2f((p1.x - m) * L2E)
                    + p2.y * ex2f((p2.x - m) * L2E) + p3.y * ex2f((p3.x - m) * L2E);
            float contrib = m + lg2f(s) * LN2 - SELF[tid];
            contrib += __shfl_xor_sync(0xFFFFFFFFu, contrib, 16);
            contrib += __shfl_xor_sync(0xFFFFFFFFu, contrib, 8);
            contrib += __shfl_xor_sync(0xFFFFFFFFu, contrib, 4);
            contrib += __shfl_xor_sync(0xFFFFFFFFu, contrib, 2);
            contrib += __shfl_xor_sync(0xFFFFFFFFu, contrib, 1);
            if (L == 0) red[wid] = contrib;
        }
        __syncthreads();
        if (tid == 0) total += red[0] + red[1] + red[2] + red[3];
        if (t2 == 0) { asm volatile("cp.async.wait_group 0;" ::: "memory"); }
        __syncthreads();
    }

    if (tid == 0) atomicAdd(out, total);
}

// ============================ launch ============================
extern "C" void kernel_launch(void* const* d_in, const int* in_sizes, int n_in,
                              void* d_out, int out_size) {
    const float* E  = (const float*)d_in[0];
    const float* wp = (const float*)d_in[1];
    const float* bp = (const float*)d_in[2];
    float* out = (float*)d_out;

    centroid_kernel<<<BB * NN / 4, 256>>>(E, out);

    cudaFuncSetAttribute(loss_kernel, cudaFuncAttributeMaxDynamicSharedMemorySize, SMEM_TOTAL);
    loss_kernel<<<128, 512, SMEM_TOTAL>>>(wp, bp, out);
}